// round 17
// baseline (speedup 1.0000x reference)
#include <cuda_runtime.h>

// SMFNet B=2,N=8192,D=64,DV=64,M=3 — chord mask = diag + superdiag(wrap).
// out[i] = w0 V0[i] + w1 V0[i+1] + w2 V0[i+2] + w3 V0[i+3]   (wrap)
//   V0 = X@Wg + bg
//   Am_j = X[j]·Wf[m][:,j] + bf[m][j],  Cm_j = X[j]·Wf[m][:,j+1] + bf[m][j+1]
// R17 = R16 with the GEMM re-paired along d: Wg staged interleaved
// (Wt[dp][e] = (Wg[2dp][e],Wg[2dp+1][e]) as u64), x read as u64 straight
// from row-major Xs -> zero pack movs, zero in-loop LDGs.
// 8 cols x 1 row per thread (cg=t&7 -> 1 wavefront per Wt LDS.128).

#define Bc   2
#define Nc   8192
#define Dc   64
#define TROWS 16           // output rows per CTA  -> 512 CTAs
#define XR    19           // staged rows per batch (TROWS + 3 halo)
#define RS    (2*XR)       // 38 row-slots
#define PAD   68           // float4-aligned row stride (272B)
#define ACW   20
#define NTHREADS 256

typedef unsigned long long u64;

// smem (floats)
#define OFF_XS  0                      // RS*PAD = 2584
#define OFF_VS  (OFF_XS + RS*PAD)      // 2584 (byte 10336, 16B-aligned)
#define OFF_WT  (OFF_VS + RS*PAD)      // 4096 (byte 20672, 16B-aligned)
#define OFF_AP  (OFF_WT + 4096)        // 2*120
#define OFF_CP  (OFF_AP + 240)         // 2*120
#define SMEM_FLOATS (OFF_CP + 240)
#define SMEM_BYTES  (SMEM_FLOATS * 4)

__device__ __forceinline__ void unpack2(u64 v, float& x, float& y) {
    asm("mov.b64 {%0, %1}, %2;" : "=f"(x), "=f"(y) : "l"(v));
}
__device__ __forceinline__ void fma2(u64& d, u64 a, u64 b) {
    asm("fma.rn.f32x2 %0, %1, %2, %3;" : "=l"(d) : "l"(a), "l"(b), "l"(d));
}

__global__ __launch_bounds__(NTHREADS, 4)
void smf_fused_kernel(const float* __restrict__ X,
                      const float* __restrict__ Wg,
                      const float* __restrict__ bg,
                      const float* __restrict__ Wf,
                      const float* __restrict__ bf,
                      float* __restrict__ out)
{
    extern __shared__ float sm[];
    float* Xs  = sm + OFF_XS;   // [RS][PAD], rs = b*XR + j
    float* Vs  = sm + OFF_VS;   // [RS][PAD]
    float* Wtf = sm + OFF_WT;   // [32][128]: u64 (dp,e) = (Wg[2dp][e],Wg[2dp+1][e])
    float* Ap  = sm + OFF_AP;   // [2][6*ACW]  d-half partials
    float* Cp  = sm + OFF_CP;

    const int t  = threadIdx.x;
    const int r0 = blockIdx.x * TROWS;

    // ---- Phase A: stage X rows (both batches, wrap) + interleaved Wg ----
    {
        const float4* X4 = reinterpret_cast<const float4*>(X);
        #pragma unroll
        for (int idx = t; idx < RS * 16; idx += NTHREADS) {
            int rs = idx >> 4, q = idx & 15;
            int b  = rs >= XR;
            int j  = rs - b * XR;
            int gi = (r0 + j) & (Nc - 1);
            *reinterpret_cast<float4*>(&Xs[rs * PAD + q * 4]) =
                __ldg(X4 + ((size_t)b * Nc + gi) * 16 + q);
        }
        #pragma unroll
        for (int idx = t; idx < 64 * 64; idx += NTHREADS) {
            int d = idx >> 6, e = idx & 63;
            Wtf[(d >> 1) * 128 + e * 2 + (d & 1)] = __ldg(Wg + idx);
        }
    }
    __syncthreads();

    // ---- Phase B1: column-shared A/C dots, d-split 2-way (228 tasks) ----
    if (t < 228) {
        const int half = t >= 114;
        const int s = t - 114 * half;
        const int c = s % 19;
        const int g = s / 19;           // 0..5
        const int m = g % 3;
        const int b = g / 3;
        const int gi  = (r0 + c) & (Nc - 1);
        const int cm1 = (c == 0) ? 0 : (c - 1);
        const int d0  = half * 32;
        const float* wp = Wf + (size_t)m * Dc * Nc + (size_t)d0 * Nc + gi;
        const float* xA = &Xs[(b * XR + c)   * PAD + d0];
        const float* xC = &Xs[(b * XR + cm1) * PAD + d0];
        float aA0 = 0.f, aA1 = 0.f, aC0 = 0.f, aC1 = 0.f;
        #pragma unroll
        for (int d = 0; d < 32; d += 2) {
            float w0 = __ldg(wp + (size_t)d * Nc);
            float w1 = __ldg(wp + (size_t)(d + 1) * Nc);
            aA0 = fmaf(xA[d],     w0, aA0);
            aA1 = fmaf(xA[d + 1], w1, aA1);
            aC0 = fmaf(xC[d],     w0, aC0);
            aC1 = fmaf(xC[d + 1], w1, aC1);
        }
        const float bfv = half ? 0.f : __ldg(bf + m * Nc + gi);
        const int si = (b * 3 + m) * ACW;
        if (c < 18) Ap[half * 120 + si + c] = aA0 + aA1 + bfv;
        if (c >= 1) Cp[half * 120 + si + (c - 1)] = aC0 + aC1 + bfv;
    }

    // ---- Phase B2: GEMM V0 = X@Wg + bg, d-paired FFMA2, no packs ----
    // thread: cols [8cg, 8cg+8) (cg = t&7), row rsb = t>>3 (0..31).
    {
        const int cg  = t & 7;
        const int rsb = t >> 3;
        const int e0  = cg * 8;
        const ulonglong2* wt =
            reinterpret_cast<const ulonglong2*>(Wtf) + cg * 4;
        const float* xrow = &Xs[rsb * PAD];

        u64 acc[8];
        #pragma unroll
        for (int c = 0; c < 8; c++) acc[c] = 0ull;

        #pragma unroll 8
        for (int dp = 0; dp < 32; dp++) {
            u64 xv = *reinterpret_cast<const u64*>(xrow + 2 * dp);
            ulonglong2 w0 = wt[dp * 32 + 0];
            ulonglong2 w1 = wt[dp * 32 + 1];
            ulonglong2 w2 = wt[dp * 32 + 2];
            ulonglong2 w3 = wt[dp * 32 + 3];
            fma2(acc[0], xv, w0.x);  fma2(acc[1], xv, w0.y);
            fma2(acc[2], xv, w1.x);  fma2(acc[3], xv, w1.y);
            fma2(acc[4], xv, w2.x);  fma2(acc[5], xv, w2.y);
            fma2(acc[6], xv, w3.x);  fma2(acc[7], xv, w3.y);
        }
        float4 bq0 = __ldg(reinterpret_cast<const float4*>(bg + e0));
        float4 bq1 = __ldg(reinterpret_cast<const float4*>(bg + e0 + 4));
        float lo, hi;
        float4 o;
        unpack2(acc[0], lo, hi);  o.x = lo + hi + bq0.x;
        unpack2(acc[1], lo, hi);  o.y = lo + hi + bq0.y;
        unpack2(acc[2], lo, hi);  o.z = lo + hi + bq0.z;
        unpack2(acc[3], lo, hi);  o.w = lo + hi + bq0.w;
        *reinterpret_cast<float4*>(&Vs[rsb * PAD + e0]) = o;
        unpack2(acc[4], lo, hi);  o.x = lo + hi + bq1.x;
        unpack2(acc[5], lo, hi);  o.y = lo + hi + bq1.y;
        unpack2(acc[6], lo, hi);  o.z = lo + hi + bq1.z;
        unpack2(acc[7], lo, hi);  o.w = lo + hi + bq1.w;
        *reinterpret_cast<float4*>(&Vs[rsb * PAD + e0 + 4]) = o;
    }

    // ---- Phase B2 tail: rows 32..37 on threads 208..255 ----
    if (t >= 208) {
        const int s2  = t - 208;
        const int cg  = s2 & 7;
        const int row = 32 + (s2 >> 3);     // 32..37
        const int e0  = cg * 8;
        const ulonglong2* wt =
            reinterpret_cast<const ulonglong2*>(Wtf) + cg * 4;
        const float* xrow = &Xs[row * PAD];

        u64 acc[8];
        #pragma unroll
        for (int c = 0; c < 8; c++) acc[c] = 0ull;

        #pragma unroll 8
        for (int dp = 0; dp < 32; dp++) {
            u64 xv = *reinterpret_cast<const u64*>(xrow + 2 * dp);
            ulonglong2 w0 = wt[dp * 32 + 0];
            ulonglong2 w1 = wt[dp * 32 + 1];
            ulonglong2 w2 = wt[dp * 32 + 2];
            ulonglong2 w3 = wt[dp * 32 + 3];
            fma2(acc[0], xv, w0.x);  fma2(acc[1], xv, w0.y);
            fma2(acc[2], xv, w1.x);  fma2(acc[3], xv, w1.y);
            fma2(acc[4], xv, w2.x);  fma2(acc[5], xv, w2.y);
            fma2(acc[6], xv, w3.x);  fma2(acc[7], xv, w3.y);
        }
        float4 bq0 = __ldg(reinterpret_cast<const float4*>(bg + e0));
        float4 bq1 = __ldg(reinterpret_cast<const float4*>(bg + e0 + 4));
        float lo, hi;
        float4 o;
        unpack2(acc[0], lo, hi);  o.x = lo + hi + bq0.x;
        unpack2(acc[1], lo, hi);  o.y = lo + hi + bq0.y;
        unpack2(acc[2], lo, hi);  o.z = lo + hi + bq0.z;
        unpack2(acc[3], lo, hi);  o.w = lo + hi + bq0.w;
        *reinterpret_cast<float4*>(&Vs[row * PAD + e0]) = o;
        unpack2(acc[4], lo, hi);  o.x = lo + hi + bq1.x;
        unpack2(acc[5], lo, hi);  o.y = lo + hi + bq1.y;
        unpack2(acc[6], lo, hi);  o.z = lo + hi + bq1.z;
        unpack2(acc[7], lo, hi);  o.w = lo + hi + bq1.w;
        *reinterpret_cast<float4*>(&Vs[row * PAD + e0 + 4]) = o;
    }
    __syncthreads();

    // ---- Phase C: weights from partials + 4-tap combine + store ----
    {
        const int e0 = (t & 15) * 4;
        const int jr = t >> 4;
        #pragma unroll
        for (int b = 0; b < Bc; b++) {
            const int s0 = (b * 3 + 0) * ACW;
            const int s1 = (b * 3 + 1) * ACW;
            const int s2 = (b * 3 + 2) * ACW;
            float A1i  = Ap[s0 + jr]     + Ap[120 + s0 + jr];
            float A1i1 = Ap[s0 + jr + 1] + Ap[120 + s0 + jr + 1];
            float A1i2 = Ap[s0 + jr + 2] + Ap[120 + s0 + jr + 2];
            float C1i  = Cp[s0 + jr]     + Cp[120 + s0 + jr];
            float C1i1 = Cp[s0 + jr + 1] + Cp[120 + s0 + jr + 1];
            float C1i2 = Cp[s0 + jr + 2] + Cp[120 + s0 + jr + 2];
            float A2i  = Ap[s1 + jr]     + Ap[120 + s1 + jr];
            float A2i1 = Ap[s1 + jr + 1] + Ap[120 + s1 + jr + 1];
            float C2i  = Cp[s1 + jr]     + Cp[120 + s1 + jr];
            float C2i1 = Cp[s1 + jr + 1] + Cp[120 + s1 + jr + 1];
            float A3   = Ap[s2 + jr]     + Ap[120 + s2 + jr];
            float C3   = Cp[s2 + jr]     + Cp[120 + s2 + jr];

            float w0 = A3 * A2i * A1i;
            float w1 = A3 * (A2i * C1i + C2i * A1i1) + C3 * A2i1 * A1i1;
            float w2 = A3 * C2i * C1i1 + C3 * (A2i1 * C1i1 + C2i1 * A1i2);
            float w3 = C3 * C2i1 * C1i2;

            const float* vb = &Vs[(b * XR + jr) * PAD + e0];
            float4 p0 = *reinterpret_cast<const float4*>(vb);
            float4 p1 = *reinterpret_cast<const float4*>(vb + PAD);
            float4 p2 = *reinterpret_cast<const float4*>(vb + 2 * PAD);
            float4 p3 = *reinterpret_cast<const float4*>(vb + 3 * PAD);

            float4 o;
            o.x = w0 * p0.x + w1 * p1.x + w2 * p2.x + w3 * p3.x;
            o.y = w0 * p0.y + w1 * p1.y + w2 * p2.y + w3 * p3.y;
            o.z = w0 * p0.z + w1 * p1.z + w2 * p2.z + w3 * p3.z;
            o.w = w0 * p0.w + w1 * p1.w + w2 * p2.w + w3 * p3.w;

            const int gi = r0 + jr;
            *reinterpret_cast<float4*>(&out[((size_t)b * Nc + gi) * 64 + e0]) = o;
        }
    }
}

extern "C" void kernel_launch(void* const* d_in, const int* in_sizes, int n_in,
                              void* d_out, int out_size)
{
    const float* X  = (const float*)d_in[0];   // (2, 8192, 64)
    const float* Wg = (const float*)d_in[1];   // (64, 64)
    const float* bg = (const float*)d_in[2];   // (64,)
    const float* Wf = (const float*)d_in[3];   // (3, 64, 8192)
    const float* bf = (const float*)d_in[4];   // (3, 8192)
    float* out = (float*)d_out;                // (2, 8192, 64)

    cudaFuncSetAttribute(smf_fused_kernel,
                         cudaFuncAttributeMaxDynamicSharedMemorySize, SMEM_BYTES);

    dim3 grid(Nc / TROWS, 1);                  // 512 CTAs
    smf_fused_kernel<<<grid, NTHREADS, SMEM_BYTES>>>(X, Wg, bg, Wf, bf, out);
}